// round 6
// baseline (speedup 1.0000x reference)
#include <cuda_runtime.h>

#define D 64
#define MAX_NODES 50000
#define CAP 128    // per-node bucket capacity; Poisson(20) max deg ~50
#define UROW 72    // padded U^T/V^T row stride (16B gap after o=31)
#define XROW 68    // padded x/agg smem tile row stride (2*68 mod 32 = 8)
#define UV_FLOATS (UROW * D)   // 4608

// Scratch (no cudaMalloc allowed).
__device__ int g_cnt[MAX_NODES];
__device__ int g_bucket[(size_t)MAX_NODES * CAP];               // 25.6 MB
__device__ __align__(16) float g_Ut[UV_FLOATS];
__device__ __align__(16) float g_Vt[UV_FLOATS];

// ---------------------------------------------------------------------------
// Packed f32x2 helpers (bit-identical to scalar fp32).
// ---------------------------------------------------------------------------
__device__ __forceinline__ void ffma2(unsigned long long& acc,
                                      unsigned long long a,
                                      unsigned long long b) {
    asm("fma.rn.f32x2 %0, %1, %2, %0;" : "+l"(acc) : "l"(a), "l"(b));
}
__device__ __forceinline__ unsigned long long dup2(float v) {
    unsigned long long r;
    asm("mov.b64 %0, {%1, %1};" : "=l"(r) : "f"(v));
    return r;
}

// ---------------------------------------------------------------------------
// Kernel 1: prep. Zero counters + padded transpose of U,V.
// ---------------------------------------------------------------------------
__global__ void prep_kernel(const float* __restrict__ U,
                            const float* __restrict__ V,
                            int nNodes) {
    int i = blockIdx.x * blockDim.x + threadIdx.x;
    if (i < nNodes) g_cnt[i] = 0;
    if (i < D * D) {
        int o = i >> 6, d = i & 63;
        int oo = o + ((o >> 5) << 2);
        g_Ut[d * UROW + oo] = U[i];
        g_Vt[d * UROW + oo] = V[i];
    }
}

// ---------------------------------------------------------------------------
// Kernel 2: bucket fill (int atomics spread over 50K counters).
// ---------------------------------------------------------------------------
__global__ void fill_buckets_kernel(const int* __restrict__ src,
                                    const int* __restrict__ dst,
                                    int nEdges) {
    int e = blockIdx.x * blockDim.x + threadIdx.x;
    if (e >= nEdges) return;
    int d = __ldg(dst + e);
    int s = __ldg(src + e);
    int pos = atomicAdd(&g_cnt[d], 1);
    if (pos < CAP)
        g_bucket[(size_t)d * CAP + pos] = s;
}

// ---------------------------------------------------------------------------
// Kernel 3: FUSED gather + dual-GEMM + ReLU.
// Block: 256 threads, tile 64 nodes x 64 outs.
// Phase A: load U/V + x tile to smem; gather agg rows for these 64 nodes
//          straight into the smem as_ tile (one warp per 8 nodes, lane owns a
//          float2 column; fp32 end-to-end). No global agg buffer at all.
// Phase B: GEMM, thread micro-tile 2 nodes x 8 outs (8 f32x2 accumulators).
// Blocks on an SM pipeline naturally: gather-phase (latency) overlaps
// GEMM-phase (FMA) of neighbors. Smem 71680 B -> 3 blocks/SM, 24 warps/SM.
// ---------------------------------------------------------------------------
#define GEMM_SMEM_BYTES ((2 * UV_FLOATS + 2 * 64 * XROW) * 4)  // 71680

__global__ __launch_bounds__(256) void fused_all(
    const float* __restrict__ x,
    float* __restrict__ out,
    int nNodes) {
    extern __shared__ __align__(16) float sm[];
    float* Ut = sm;                        // 4608
    float* Vt = sm + UV_FLOATS;            // 4608
    float* xs = sm + 2 * UV_FLOATS;        // 64*68
    float* as_ = xs + 64 * XROW;           // 64*68

    int tid = threadIdx.x;
    int nodeBase = blockIdx.x * 64;

    // --- Phase A1: copy padded U^T/V^T (1152 float4 each) ---
    {
        const float4* gU = reinterpret_cast<const float4*>(g_Ut);
        const float4* gV = reinterpret_cast<const float4*>(g_Vt);
        float4* sU = reinterpret_cast<float4*>(Ut);
        float4* sV = reinterpret_cast<float4*>(Vt);
        #pragma unroll
        for (int k = 0; k < 5; k++) {
            int idx = tid + k * 256;
            if (idx < 1152) {
                sU[idx] = gU[idx];
                sV[idx] = gV[idx];
            }
        }
    }
    // --- Phase A2: x tile (64 rows x 16 float4, coalesced) ---
    #pragma unroll
    for (int k = 0; k < 4; k++) {
        int i4 = tid + k * 256;            // 0..1023
        int n = i4 >> 4;
        int dc = (i4 & 15) << 2;
        int gn = nodeBase + n;
        float4 xv = make_float4(0.f, 0.f, 0.f, 0.f);
        if (gn < nNodes)
            xv = *reinterpret_cast<const float4*>(x + (size_t)gn * D + dc);
        *reinterpret_cast<float4*>(xs + n * XROW + dc) = xv;
    }
    // --- Phase A3: gather agg for these 64 nodes into as_ ---
    {
        int wid = tid >> 5;
        int lane = tid & 31;
        const float2* x2 = reinterpret_cast<const float2*>(x);
        #pragma unroll 1
        for (int k = 0; k < 8; k++) {
            int n = (wid << 3) + k;
            int gn = nodeBase + n;
            float2 acc = make_float2(0.f, 0.f);
            if (gn < nNodes) {
                int cnt = __ldg(g_cnt + gn);
                cnt = cnt < CAP ? cnt : CAP;
                const int* row = g_bucket + (size_t)gn * CAP;
                int e = 0;
                for (; e + 4 <= cnt; e += 4) {
                    int s0 = __ldg(row + e + 0);
                    int s1 = __ldg(row + e + 1);
                    int s2 = __ldg(row + e + 2);
                    int s3 = __ldg(row + e + 3);
                    float2 v0 = __ldg(x2 + (size_t)s0 * 32 + lane);
                    float2 v1 = __ldg(x2 + (size_t)s1 * 32 + lane);
                    float2 v2 = __ldg(x2 + (size_t)s2 * 32 + lane);
                    float2 v3 = __ldg(x2 + (size_t)s3 * 32 + lane);
                    acc.x += (v0.x + v1.x) + (v2.x + v3.x);
                    acc.y += (v0.y + v1.y) + (v2.y + v3.y);
                }
                for (; e < cnt; e++) {
                    int s = __ldg(row + e);
                    float2 v = __ldg(x2 + (size_t)s * 32 + lane);
                    acc.x += v.x;
                    acc.y += v.y;
                }
            }
            *reinterpret_cast<float2*>(as_ + n * XROW + (lane << 1)) = acc;
        }
    }
    __syncthreads();

    // --- Phase B: GEMM, 2 nodes x 8 outs per thread ---
    int ti = tid & 7;      // out group:  outs [8*ti, 8*ti+7]
    int tj = tid >> 3;     // node group: nodes [2*tj, 2*tj+1]
    int n0 = tj << 1;

    unsigned long long acc[2][4];
    #pragma unroll
    for (int r = 0; r < 2; r++)
        #pragma unroll
        for (int q = 0; q < 4; q++) acc[r][q] = 0ull;

    const float* up = Ut + ti * 8 + ((ti >> 2) << 2);
    const float* vp = Vt + ti * 8 + ((ti >> 2) << 2);
    const float* xp = xs + n0 * XROW;
    const float* ap = as_ + n0 * XROW;

    #pragma unroll 4
    for (int d = 0; d < 64; d += 2) {
        ulonglong2 u0 = *reinterpret_cast<const ulonglong2*>(up + d * UROW);
        ulonglong2 u0h = *reinterpret_cast<const ulonglong2*>(up + d * UROW + 4);
        ulonglong2 u1 = *reinterpret_cast<const ulonglong2*>(up + (d + 1) * UROW);
        ulonglong2 u1h = *reinterpret_cast<const ulonglong2*>(up + (d + 1) * UROW + 4);
        ulonglong2 v0 = *reinterpret_cast<const ulonglong2*>(vp + d * UROW);
        ulonglong2 v0h = *reinterpret_cast<const ulonglong2*>(vp + d * UROW + 4);
        ulonglong2 v1 = *reinterpret_cast<const ulonglong2*>(vp + (d + 1) * UROW);
        ulonglong2 v1h = *reinterpret_cast<const ulonglong2*>(vp + (d + 1) * UROW + 4);
        #pragma unroll
        for (int r = 0; r < 2; r++) {
            float2 xr = *reinterpret_cast<const float2*>(xp + r * XROW + d);
            float2 ar = *reinterpret_cast<const float2*>(ap + r * XROW + d);
            unsigned long long x0 = dup2(xr.x), x1 = dup2(xr.y);
            unsigned long long a0 = dup2(ar.x), a1 = dup2(ar.y);
            ffma2(acc[r][0], x0, u0.x);
            ffma2(acc[r][1], x0, u0.y);
            ffma2(acc[r][2], x0, u0h.x);
            ffma2(acc[r][3], x0, u0h.y);
            ffma2(acc[r][0], a0, v0.x);
            ffma2(acc[r][1], a0, v0.y);
            ffma2(acc[r][2], a0, v0h.x);
            ffma2(acc[r][3], a0, v0h.y);
            ffma2(acc[r][0], x1, u1.x);
            ffma2(acc[r][1], x1, u1.y);
            ffma2(acc[r][2], x1, u1h.x);
            ffma2(acc[r][3], x1, u1h.y);
            ffma2(acc[r][0], a1, v1.x);
            ffma2(acc[r][1], a1, v1.y);
            ffma2(acc[r][2], a1, v1h.x);
            ffma2(acc[r][3], a1, v1h.y);
        }
    }

    int o0 = ti << 3;
    #pragma unroll
    for (int r = 0; r < 2; r++) {
        int gn = nodeBase + n0 + r;
        if (gn < nNodes) {
            float f[8];
            #pragma unroll
            for (int q = 0; q < 4; q++)
                asm("mov.b64 {%0, %1}, %2;"
                    : "=f"(f[2 * q]), "=f"(f[2 * q + 1]) : "l"(acc[r][q]));
            float4 o_lo, o_hi;
            o_lo.x = fmaxf(f[0], 0.f); o_lo.y = fmaxf(f[1], 0.f);
            o_lo.z = fmaxf(f[2], 0.f); o_lo.w = fmaxf(f[3], 0.f);
            o_hi.x = fmaxf(f[4], 0.f); o_hi.y = fmaxf(f[5], 0.f);
            o_hi.z = fmaxf(f[6], 0.f); o_hi.w = fmaxf(f[7], 0.f);
            float* op = out + (size_t)gn * D + o0;
            *reinterpret_cast<float4*>(op) = o_lo;
            *reinterpret_cast<float4*>(op + 4) = o_hi;
        }
    }
}

// ---------------------------------------------------------------------------
// Launch: prep -> bucket fill -> fused gather+GEMM.
// ---------------------------------------------------------------------------
extern "C" void kernel_launch(void* const* d_in, const int* in_sizes, int n_in,
                              void* d_out, int out_size) {
    const float* x   = (const float*)d_in[0];
    const int*   src = (const int*)d_in[1];
    const int*   dst = (const int*)d_in[2];
    const float* U   = (const float*)d_in[3];
    const float* V   = (const float*)d_in[4];
    float* out = (float*)d_out;

    int nNodes = in_sizes[0] / D;
    int nEdges = in_sizes[1];

    cudaFuncSetAttribute(fused_all,
                         cudaFuncAttributeMaxDynamicSharedMemorySize,
                         GEMM_SMEM_BYTES);

    int prepN = nNodes > D * D ? nNodes : D * D;
    prep_kernel<<<(prepN + 255) / 256, 256>>>(U, V, nNodes);

    fill_buckets_kernel<<<(nEdges + 255) / 256, 256>>>(src, dst, nEdges);

    fused_all<<<(nNodes + 63) / 64, 256, GEMM_SMEM_BYTES>>>(x, out, nNodes);
}

// round 7
// speedup vs baseline: 1.2431x; 1.2431x over previous
#include <cuda_runtime.h>

#define D 64
#define MAX_NODES 50000
#define CAP 128    // per-node bucket capacity; Poisson(20) max deg ~50
#define UROW 72    // padded U^T/V^T row stride (16B gap after o=31)
#define XROW 68    // padded x/agg smem tile row stride
#define UV_FLOATS (UROW * D)   // 4608

// Scratch (no cudaMalloc allowed).
__device__ __align__(16) float g_agg[(size_t)MAX_NODES * D];   // 12.8 MB
__device__ int g_cnt[MAX_NODES];
__device__ int g_bucket[(size_t)MAX_NODES * CAP];               // 25.6 MB
__device__ __align__(16) float g_Ut[UV_FLOATS];
__device__ __align__(16) float g_Vt[UV_FLOATS];

// ---------------------------------------------------------------------------
// Packed f32x2 helpers (bit-identical to scalar fp32).
// ---------------------------------------------------------------------------
__device__ __forceinline__ void ffma2(unsigned long long& acc,
                                      unsigned long long a,
                                      unsigned long long b) {
    asm("fma.rn.f32x2 %0, %1, %2, %0;" : "+l"(acc) : "l"(a), "l"(b));
}
__device__ __forceinline__ unsigned long long dup2(float v) {
    unsigned long long r;
    asm("mov.b64 %0, {%1, %1};" : "=l"(r) : "f"(v));
    return r;
}

// ---------------------------------------------------------------------------
// Kernel 1: prep. Zero counters + padded transpose of U,V.
// ---------------------------------------------------------------------------
__global__ void prep_kernel(const float* __restrict__ U,
                            const float* __restrict__ V,
                            int nNodes) {
    int i = blockIdx.x * blockDim.x + threadIdx.x;
    if (i < nNodes) g_cnt[i] = 0;
    if (i < D * D) {
        int o = i >> 6, d = i & 63;
        int oo = o + ((o >> 5) << 2);
        g_Ut[d * UROW + oo] = U[i];
        g_Vt[d * UROW + oo] = V[i];
    }
}

// ---------------------------------------------------------------------------
// Kernel 2: bucket fill (int atomics spread over 50K counters).
// ---------------------------------------------------------------------------
__global__ void fill_buckets_kernel(const int* __restrict__ src,
                                    const int* __restrict__ dst,
                                    int nEdges) {
    int e = blockIdx.x * blockDim.x + threadIdx.x;
    if (e >= nEdges) return;
    int d = __ldg(dst + e);
    int s = __ldg(src + e);
    int pos = atomicAdd(&g_cnt[d], 1);
    if (pos < CAP)
        g_bucket[(size_t)d * CAP + pos] = s;
}

// ---------------------------------------------------------------------------
// Kernel 3: pull-gather (fp32, R4 version — best measured). One warp per
// node; lane owns a float2 column. High occupancy hides the chain latency.
// ---------------------------------------------------------------------------
__global__ __launch_bounds__(256) void gather_kernel(
    const float* __restrict__ x, int nNodes) {
    int warp = (blockIdx.x * blockDim.x + threadIdx.x) >> 5;
    if (warp >= nNodes) return;
    int lane = threadIdx.x & 31;

    int cnt = __ldg(g_cnt + warp);
    cnt = cnt < CAP ? cnt : CAP;
    const int* row = g_bucket + (size_t)warp * CAP;
    const float2* x2 = reinterpret_cast<const float2*>(x);

    float2 acc = make_float2(0.f, 0.f);
    int e = 0;
    for (; e + 4 <= cnt; e += 4) {
        int s0 = __ldg(row + e + 0);
        int s1 = __ldg(row + e + 1);
        int s2 = __ldg(row + e + 2);
        int s3 = __ldg(row + e + 3);
        float2 v0 = __ldg(x2 + (size_t)s0 * 32 + lane);
        float2 v1 = __ldg(x2 + (size_t)s1 * 32 + lane);
        float2 v2 = __ldg(x2 + (size_t)s2 * 32 + lane);
        float2 v3 = __ldg(x2 + (size_t)s3 * 32 + lane);
        acc.x += (v0.x + v1.x) + (v2.x + v3.x);
        acc.y += (v0.y + v1.y) + (v2.y + v3.y);
    }
    for (; e < cnt; e++) {
        int s = __ldg(row + e);
        float2 v = __ldg(x2 + (size_t)s * 32 + lane);
        acc.x += v.x;
        acc.y += v.y;
    }
    reinterpret_cast<float2*>(g_agg)[(size_t)warp * 32 + lane] = acc;
}

// ---------------------------------------------------------------------------
// Kernel 4: dual-GEMM + ReLU. 256 threads, tile 64 nodes x 64 outs, thread
// micro-tile 2 nodes x 8 outs (8 f32x2 accumulators). Smem 71680 B ->
// 3 blocks/SM, 24 warps/SM (vs 12 in R4) to cover LDS latency.
// ---------------------------------------------------------------------------
#define GEMM_SMEM_BYTES ((2 * UV_FLOATS + 2 * 64 * XROW) * 4)  // 71680

__global__ __launch_bounds__(256) void fused_gemm_relu(
    const float* __restrict__ x,
    float* __restrict__ out,
    int nNodes) {
    extern __shared__ __align__(16) float sm[];
    float* Ut = sm;                        // 4608
    float* Vt = sm + UV_FLOATS;            // 4608
    float* xs = sm + 2 * UV_FLOATS;        // 64*68
    float* as_ = xs + 64 * XROW;           // 64*68

    int tid = threadIdx.x;
    int nodeBase = blockIdx.x * 64;

    // Copy padded U^T/V^T (1152 float4 each).
    {
        const float4* gU = reinterpret_cast<const float4*>(g_Ut);
        const float4* gV = reinterpret_cast<const float4*>(g_Vt);
        float4* sU = reinterpret_cast<float4*>(Ut);
        float4* sV = reinterpret_cast<float4*>(Vt);
        #pragma unroll
        for (int k = 0; k < 5; k++) {
            int idx = tid + k * 256;
            if (idx < 1152) {
                sU[idx] = gU[idx];
                sV[idx] = gV[idx];
            }
        }
    }
    // x/agg tiles: 64 rows x 16 float4, coalesced reads, padded writes.
    #pragma unroll
    for (int k = 0; k < 4; k++) {
        int i4 = tid + k * 256;            // 0..1023
        int n = i4 >> 4;
        int dc = (i4 & 15) << 2;
        int gn = nodeBase + n;
        float4 xv = make_float4(0.f, 0.f, 0.f, 0.f);
        float4 av = xv;
        if (gn < nNodes) {
            xv = *reinterpret_cast<const float4*>(x + (size_t)gn * D + dc);
            av = *reinterpret_cast<const float4*>(g_agg + (size_t)gn * D + dc);
        }
        *reinterpret_cast<float4*>(xs + n * XROW + dc) = xv;
        *reinterpret_cast<float4*>(as_ + n * XROW + dc) = av;
    }
    __syncthreads();

    int ti = tid & 7;      // out group:  outs [8*ti, 8*ti+7]
    int tj = tid >> 3;     // node group: nodes [2*tj, 2*tj+1]
    int n0 = tj << 1;

    unsigned long long acc[2][4];
    #pragma unroll
    for (int r = 0; r < 2; r++)
        #pragma unroll
        for (int q = 0; q < 4; q++) acc[r][q] = 0ull;

    const float* up = Ut + ti * 8 + ((ti >> 2) << 2);
    const float* vp = Vt + ti * 8 + ((ti >> 2) << 2);
    const float* xp = xs + n0 * XROW;
    const float* ap = as_ + n0 * XROW;

    #pragma unroll 4
    for (int d = 0; d < 64; d += 2) {
        ulonglong2 u0 = *reinterpret_cast<const ulonglong2*>(up + d * UROW);
        ulonglong2 u0h = *reinterpret_cast<const ulonglong2*>(up + d * UROW + 4);
        ulonglong2 u1 = *reinterpret_cast<const ulonglong2*>(up + (d + 1) * UROW);
        ulonglong2 u1h = *reinterpret_cast<const ulonglong2*>(up + (d + 1) * UROW + 4);
        ulonglong2 v0 = *reinterpret_cast<const ulonglong2*>(vp + d * UROW);
        ulonglong2 v0h = *reinterpret_cast<const ulonglong2*>(vp + d * UROW + 4);
        ulonglong2 v1 = *reinterpret_cast<const ulonglong2*>(vp + (d + 1) * UROW);
        ulonglong2 v1h = *reinterpret_cast<const ulonglong2*>(vp + (d + 1) * UROW + 4);
        #pragma unroll
        for (int r = 0; r < 2; r++) {
            float2 xr = *reinterpret_cast<const float2*>(xp + r * XROW + d);
            float2 ar = *reinterpret_cast<const float2*>(ap + r * XROW + d);
            unsigned long long x0 = dup2(xr.x), x1 = dup2(xr.y);
            unsigned long long a0 = dup2(ar.x), a1 = dup2(ar.y);
            ffma2(acc[r][0], x0, u0.x);
            ffma2(acc[r][1], x0, u0.y);
            ffma2(acc[r][2], x0, u0h.x);
            ffma2(acc[r][3], x0, u0h.y);
            ffma2(acc[r][0], a0, v0.x);
            ffma2(acc[r][1], a0, v0.y);
            ffma2(acc[r][2], a0, v0h.x);
            ffma2(acc[r][3], a0, v0h.y);
            ffma2(acc[r][0], x1, u1.x);
            ffma2(acc[r][1], x1, u1.y);
            ffma2(acc[r][2], x1, u1h.x);
            ffma2(acc[r][3], x1, u1h.y);
            ffma2(acc[r][0], a1, v1.x);
            ffma2(acc[r][1], a1, v1.y);
            ffma2(acc[r][2], a1, v1h.x);
            ffma2(acc[r][3], a1, v1h.y);
        }
    }

    int o0 = ti << 3;
    #pragma unroll
    for (int r = 0; r < 2; r++) {
        int gn = nodeBase + n0 + r;
        if (gn < nNodes) {
            float f[8];
            #pragma unroll
            for (int q = 0; q < 4; q++)
                asm("mov.b64 {%0, %1}, %2;"
                    : "=f"(f[2 * q]), "=f"(f[2 * q + 1]) : "l"(acc[r][q]));
            float4 o_lo, o_hi;
            o_lo.x = fmaxf(f[0], 0.f); o_lo.y = fmaxf(f[1], 0.f);
            o_lo.z = fmaxf(f[2], 0.f); o_lo.w = fmaxf(f[3], 0.f);
            o_hi.x = fmaxf(f[4], 0.f); o_hi.y = fmaxf(f[5], 0.f);
            o_hi.z = fmaxf(f[6], 0.f); o_hi.w = fmaxf(f[7], 0.f);
            float* op = out + (size_t)gn * D + o0;
            *reinterpret_cast<float4*>(op) = o_lo;
            *reinterpret_cast<float4*>(op + 4) = o_hi;
        }
    }
}

// ---------------------------------------------------------------------------
// Launch: prep -> bucket fill -> pull gather -> GEMM.
// ---------------------------------------------------------------------------
extern "C" void kernel_launch(void* const* d_in, const int* in_sizes, int n_in,
                              void* d_out, int out_size) {
    const float* x   = (const float*)d_in[0];
    const int*   src = (const int*)d_in[1];
    const int*   dst = (const int*)d_in[2];
    const float* U   = (const float*)d_in[3];
    const float* V   = (const float*)d_in[4];
    float* out = (float*)d_out;

    int nNodes = in_sizes[0] / D;
    int nEdges = in_sizes[1];

    cudaFuncSetAttribute(fused_gemm_relu,
                         cudaFuncAttributeMaxDynamicSharedMemorySize,
                         GEMM_SMEM_BYTES);

    int prepN = nNodes > D * D ? nNodes : D * D;
    prep_kernel<<<(prepN + 255) / 256, 256>>>(U, V, nNodes);

    fill_buckets_kernel<<<(nEdges + 255) / 256, 256>>>(src, dst, nEdges);

    int gblocks = (nNodes * 32 + 255) / 256;
    gather_kernel<<<gblocks, 256>>>(x, nNodes);

    fused_gemm_relu<<<(nNodes + 63) / 64, 256, GEMM_SMEM_BYTES>>>(x, out, nNodes);
}

// round 8
// speedup vs baseline: 1.4366x; 1.1556x over previous
#include <cuda_runtime.h>

#define D 64
#define MAX_NODES 50000
#define CAP 128    // per-node bucket capacity; Poisson(20) max deg ~50
#define UROW 72    // padded U^T/V^T row stride (16B gap after o=31)
#define XROW 68    // padded x/agg smem tile row stride (68 mod 32 = 4)
#define UV_FLOATS (UROW * D)   // 4608

// Scratch (no cudaMalloc allowed).
__device__ __align__(16) float g_agg[(size_t)MAX_NODES * D];   // 12.8 MB
__device__ int g_cnt[MAX_NODES];
__device__ int g_bucket[(size_t)MAX_NODES * CAP];               // 25.6 MB
__device__ __align__(16) float g_Ut[UV_FLOATS];
__device__ __align__(16) float g_Vt[UV_FLOATS];

// ---------------------------------------------------------------------------
// Packed f32x2 helpers (bit-identical to scalar fp32).
// ---------------------------------------------------------------------------
__device__ __forceinline__ void ffma2(unsigned long long& acc,
                                      unsigned long long a,
                                      unsigned long long b) {
    asm("fma.rn.f32x2 %0, %1, %2, %0;" : "+l"(acc) : "l"(a), "l"(b));
}
__device__ __forceinline__ unsigned long long dup2(float v) {
    unsigned long long r;
    asm("mov.b64 %0, {%1, %1};" : "=l"(r) : "f"(v));
    return r;
}

// ---------------------------------------------------------------------------
// Kernel 1: prep. Zero counters + padded transpose of U,V.
// ---------------------------------------------------------------------------
__global__ void prep_kernel(const float* __restrict__ U,
                            const float* __restrict__ V,
                            int nNodes) {
    int i = blockIdx.x * blockDim.x + threadIdx.x;
    if (i < nNodes) g_cnt[i] = 0;
    if (i < D * D) {
        int o = i >> 6, d = i & 63;
        int oo = o + ((o >> 5) << 2);
        g_Ut[d * UROW + oo] = U[i];
        g_Vt[d * UROW + oo] = V[i];
    }
}

// ---------------------------------------------------------------------------
// Kernel 2: bucket fill, 4 edges per thread via int4 loads.
// ---------------------------------------------------------------------------
__global__ void fill_buckets_kernel(const int* __restrict__ src,
                                    const int* __restrict__ dst,
                                    int nEdges) {
    int q = blockIdx.x * blockDim.x + threadIdx.x;
    int e0 = q << 2;
    if (e0 + 4 <= nEdges) {
        int4 s4 = __ldg(reinterpret_cast<const int4*>(src + e0));
        int4 d4 = __ldg(reinterpret_cast<const int4*>(dst + e0));
        int p0 = atomicAdd(&g_cnt[d4.x], 1);
        int p1 = atomicAdd(&g_cnt[d4.y], 1);
        int p2 = atomicAdd(&g_cnt[d4.z], 1);
        int p3 = atomicAdd(&g_cnt[d4.w], 1);
        if (p0 < CAP) g_bucket[(size_t)d4.x * CAP + p0] = s4.x;
        if (p1 < CAP) g_bucket[(size_t)d4.y * CAP + p1] = s4.y;
        if (p2 < CAP) g_bucket[(size_t)d4.z * CAP + p2] = s4.z;
        if (p3 < CAP) g_bucket[(size_t)d4.w * CAP + p3] = s4.w;
    } else {
        for (int e = e0; e < nEdges; e++) {
            int d = __ldg(dst + e);
            int s = __ldg(src + e);
            int pos = atomicAdd(&g_cnt[d], 1);
            if (pos < CAP) g_bucket[(size_t)d * CAP + pos] = s;
        }
    }
}

// ---------------------------------------------------------------------------
// Kernel 3: pull-gather, one warp per node, lane owns a float2 column.
// 8-edge unroll level for MLP=8 on the dependent load chain.
// ---------------------------------------------------------------------------
__global__ __launch_bounds__(256) void gather_kernel(
    const float* __restrict__ x, int nNodes) {
    int warp = (blockIdx.x * blockDim.x + threadIdx.x) >> 5;
    if (warp >= nNodes) return;
    int lane = threadIdx.x & 31;

    int cnt = __ldg(g_cnt + warp);
    cnt = cnt < CAP ? cnt : CAP;
    const int* row = g_bucket + (size_t)warp * CAP;
    const float2* x2 = reinterpret_cast<const float2*>(x);

    float2 acc = make_float2(0.f, 0.f);
    int e = 0;
    for (; e + 8 <= cnt; e += 8) {
        int s[8];
        #pragma unroll
        for (int k = 0; k < 8; k++) s[k] = __ldg(row + e + k);
        float2 v[8];
        #pragma unroll
        for (int k = 0; k < 8; k++) v[k] = __ldg(x2 + (size_t)s[k] * 32 + lane);
        #pragma unroll
        for (int k = 0; k < 8; k++) { acc.x += v[k].x; acc.y += v[k].y; }
    }
    for (; e + 4 <= cnt; e += 4) {
        int s0 = __ldg(row + e + 0);
        int s1 = __ldg(row + e + 1);
        int s2 = __ldg(row + e + 2);
        int s3 = __ldg(row + e + 3);
        float2 v0 = __ldg(x2 + (size_t)s0 * 32 + lane);
        float2 v1 = __ldg(x2 + (size_t)s1 * 32 + lane);
        float2 v2 = __ldg(x2 + (size_t)s2 * 32 + lane);
        float2 v3 = __ldg(x2 + (size_t)s3 * 32 + lane);
        acc.x += (v0.x + v1.x) + (v2.x + v3.x);
        acc.y += (v0.y + v1.y) + (v2.y + v3.y);
    }
    for (; e < cnt; e++) {
        int s = __ldg(row + e);
        float2 v = __ldg(x2 + (size_t)s * 32 + lane);
        acc.x += v.x;
        acc.y += v.y;
    }
    reinterpret_cast<float2*>(g_agg)[(size_t)warp * 32 + lane] = acc;
}

// ---------------------------------------------------------------------------
// Kernel 4: dual-GEMM + ReLU. 128 threads, block tile 128 nodes x 64 outs.
// Thread micro-tile: 8 nodes x 8 outs (32 f32x2 accumulators). Thread tj owns
// nodes {tj + 16r} (interleaved so the 4 tj-groups per warp hit distinct
// banks: row delta = 68 words = 4 mod 32). Per 2-d per warp: 8 LDS.128
// (32 wf) + 16 LDS.64 (32 wf) feed 128 FFMA2 -> 0.5 wf/FFMA2; LDS floor ==
// FMA floor ~12.4us. Smem 106,496 B -> 2 blocks/SM.
// ---------------------------------------------------------------------------
#define GEMM_SMEM_BYTES ((2 * UV_FLOATS + 2 * 128 * XROW) * 4)  // 106496

__global__ __launch_bounds__(128) void fused_gemm_relu(
    const float* __restrict__ x,
    float* __restrict__ out,
    int nNodes) {
    extern __shared__ __align__(16) float sm[];
    float* Ut = sm;                        // 4608
    float* Vt = sm + UV_FLOATS;            // 4608
    float* xs = sm + 2 * UV_FLOATS;        // 128*68
    float* as_ = xs + 128 * XROW;          // 128*68

    int tid = threadIdx.x;
    int nodeBase = blockIdx.x * 128;

    // Copy padded U^T/V^T (1152 float4 each).
    {
        const float4* gU = reinterpret_cast<const float4*>(g_Ut);
        const float4* gV = reinterpret_cast<const float4*>(g_Vt);
        float4* sU = reinterpret_cast<float4*>(Ut);
        float4* sV = reinterpret_cast<float4*>(Vt);
        #pragma unroll
        for (int k = 0; k < 9; k++) {
            sU[tid + k * 128] = gU[tid + k * 128];
            sV[tid + k * 128] = gV[tid + k * 128];
        }
    }
    // x/agg tiles: 128 rows x 16 float4 (coalesced reads, padded writes).
    #pragma unroll
    for (int k = 0; k < 16; k++) {
        int i4 = tid + k * 128;            // 0..2047
        int n = i4 >> 4;
        int dc = (i4 & 15) << 2;
        int gn = nodeBase + n;
        float4 xv = make_float4(0.f, 0.f, 0.f, 0.f);
        float4 av = xv;
        if (gn < nNodes) {
            xv = *reinterpret_cast<const float4*>(x + (size_t)gn * D + dc);
            av = *reinterpret_cast<const float4*>(g_agg + (size_t)gn * D + dc);
        }
        *reinterpret_cast<float4*>(xs + n * XROW + dc) = xv;
        *reinterpret_cast<float4*>(as_ + n * XROW + dc) = av;
    }
    __syncthreads();

    int ti = tid & 7;      // out group:  outs [8*ti, 8*ti+7]
    int tj = tid >> 3;     // owns nodes {tj + 16r}, r = 0..7

    unsigned long long acc[8][4];
    #pragma unroll
    for (int r = 0; r < 8; r++)
        #pragma unroll
        for (int q = 0; q < 4; q++) acc[r][q] = 0ull;

    const float* up = Ut + ti * 8 + ((ti >> 2) << 2);
    const float* vp = Vt + ti * 8 + ((ti >> 2) << 2);
    const float* xp = xs + tj * XROW;
    const float* ap = as_ + tj * XROW;

    #pragma unroll 2
    for (int d = 0; d < 64; d += 2) {
        ulonglong2 u0 = *reinterpret_cast<const ulonglong2*>(up + d * UROW);
        ulonglong2 u0h = *reinterpret_cast<const ulonglong2*>(up + d * UROW + 4);
        ulonglong2 u1 = *reinterpret_cast<const ulonglong2*>(up + (d + 1) * UROW);
        ulonglong2 u1h = *reinterpret_cast<const ulonglong2*>(up + (d + 1) * UROW + 4);
        ulonglong2 v0 = *reinterpret_cast<const ulonglong2*>(vp + d * UROW);
        ulonglong2 v0h = *reinterpret_cast<const ulonglong2*>(vp + d * UROW + 4);
        ulonglong2 v1 = *reinterpret_cast<const ulonglong2*>(vp + (d + 1) * UROW);
        ulonglong2 v1h = *reinterpret_cast<const ulonglong2*>(vp + (d + 1) * UROW + 4);
        #pragma unroll
        for (int r = 0; r < 8; r++) {
            float2 xr = *reinterpret_cast<const float2*>(xp + r * 16 * XROW + d);
            float2 ar = *reinterpret_cast<const float2*>(ap + r * 16 * XROW + d);
            unsigned long long x0 = dup2(xr.x), x1 = dup2(xr.y);
            unsigned long long a0 = dup2(ar.x), a1 = dup2(ar.y);
            ffma2(acc[r][0], x0, u0.x);
            ffma2(acc[r][1], x0, u0.y);
            ffma2(acc[r][2], x0, u0h.x);
            ffma2(acc[r][3], x0, u0h.y);
            ffma2(acc[r][0], a0, v0.x);
            ffma2(acc[r][1], a0, v0.y);
            ffma2(acc[r][2], a0, v0h.x);
            ffma2(acc[r][3], a0, v0h.y);
            ffma2(acc[r][0], x1, u1.x);
            ffma2(acc[r][1], x1, u1.y);
            ffma2(acc[r][2], x1, u1h.x);
            ffma2(acc[r][3], x1, u1h.y);
            ffma2(acc[r][0], a1, v1.x);
            ffma2(acc[r][1], a1, v1.y);
            ffma2(acc[r][2], a1, v1h.x);
            ffma2(acc[r][3], a1, v1h.y);
        }
    }

    int o0 = ti << 3;
    #pragma unroll
    for (int r = 0; r < 8; r++) {
        int gn = nodeBase + tj + 16 * r;
        if (gn < nNodes) {
            float f[8];
            #pragma unroll
            for (int q = 0; q < 4; q++)
                asm("mov.b64 {%0, %1}, %2;"
                    : "=f"(f[2 * q]), "=f"(f[2 * q + 1]) : "l"(acc[r][q]));
            float4 o_lo, o_hi;
            o_lo.x = fmaxf(f[0], 0.f); o_lo.y = fmaxf(f[1], 0.f);
            o_lo.z = fmaxf(f[2], 0.f); o_lo.w = fmaxf(f[3], 0.f);
            o_hi.x = fmaxf(f[4], 0.f); o_hi.y = fmaxf(f[5], 0.f);
            o_hi.z = fmaxf(f[6], 0.f); o_hi.w = fmaxf(f[7], 0.f);
            float* op = out + (size_t)gn * D + o0;
            *reinterpret_cast<float4*>(op) = o_lo;
            *reinterpret_cast<float4*>(op + 4) = o_hi;
        }
    }
}

// ---------------------------------------------------------------------------
// Launch: prep -> bucket fill -> pull gather -> GEMM.
// ---------------------------------------------------------------------------
extern "C" void kernel_launch(void* const* d_in, const int* in_sizes, int n_in,
                              void* d_out, int out_size) {
    const float* x   = (const float*)d_in[0];
    const int*   src = (const int*)d_in[1];
    const int*   dst = (const int*)d_in[2];
    const float* U   = (const float*)d_in[3];
    const float* V   = (const float*)d_in[4];
    float* out = (float*)d_out;

    int nNodes = in_sizes[0] / D;
    int nEdges = in_sizes[1];

    cudaFuncSetAttribute(fused_gemm_relu,
                         cudaFuncAttributeMaxDynamicSharedMemorySize,
                         GEMM_SMEM_BYTES);

    int prepN = nNodes > D * D ? nNodes : D * D;
    prep_kernel<<<(prepN + 255) / 256, 256>>>(U, V, nNodes);

    int fq = (nEdges + 3) / 4;
    fill_buckets_kernel<<<(fq + 255) / 256, 256>>>(src, dst, nEdges);

    int gblocks = (nNodes * 32 + 255) / 256;
    gather_kernel<<<gblocks, 256>>>(x, nNodes);

    fused_gemm_relu<<<(nNodes + 127) / 128, 128, GEMM_SMEM_BYTES>>>(x, out, nNodes);
}